// round 6
// baseline (speedup 1.0000x reference)
#include <cuda_runtime.h>
#include <cuda_fp16.h>
#include <math.h>
#include <stdint.h>

#define NMAX  100000
#define EMAX  1600000
#define FIN   512
#define H1    8
#define D1    64      // H1 * C1
#define NCLS  40
#define SLOPE 0.2f
#define SCAN_B 1024

// dynamic smem for k_gemm1: As[2][128][36] then Bs[2][32][72]
#define GEMM1_SMEM_FLOATS (2*128*36 + 2*32*72)   // 13824 floats = 55296 B
#define AS_OFF 0
#define BS_OFF (2*128*36)

// ---------------- scratch (static device globals; no allocations) ----------
__device__ int g_is64;
__device__ __align__(256) int    g_csr [EMAX];      // src ids grouped by dst
__device__ __align__(256) int    g_deg [NMAX];
__device__ __align__(256) int    g_row [NMAX + 1];  // CSR row pointers
__device__ __align__(256) int    g_cur [NMAX];
__device__ __align__(256) int    g_bsum[SCAN_B];
__device__ __align__(256) __half g_h1h [NMAX * D1];    // h1 in fp16 (gathered)
__device__ __align__(256) float  g_as1 [NMAX * H1];
__device__ __align__(256) float  g_ad1 [NMAX * H1];
__device__ __align__(256) __half g_hacth[NMAX * D1];   // hact in fp16
__device__ __align__(256) __half g_h2h [NMAX * NCLS];  // h2 in fp16 (gathered)
__device__ __align__(256) float  g_as2 [NMAX];
__device__ __align__(256) float  g_ad2 [NMAX];

__device__ __forceinline__ float lrelu(float v) { return v > 0.f ? v : SLOPE * v; }

// ---------------- zero degrees + detect int64 vs int32 ----------------------
__global__ void k_zero_detect(const int* __restrict__ ei, int n) {
    int i = blockIdx.x * blockDim.x + threadIdx.x;
    if (i < n) g_deg[i] = 0;
    if (i == 0) {
        int nz = 0;
        for (int k = 1; k < 64; k += 2) nz |= ei[k];   // int64 high words all zero?
        g_is64 = (nz == 0) ? 1 : 0;
    }
}

// histogram of destinations (reads only the dst column of edge_index)
__global__ void k_build(const void* __restrict__ ei, int E) {
    int i = blockIdx.x * blockDim.x + threadIdx.x;
    if (i >= E) return;
    int d;
    if (g_is64) {
        const long long* p = (const long long*)ei;
        d = (int)p[(long long)E + i];
    } else {
        const int* p = (const int*)ei;
        d = p[E + i];
    }
    atomicAdd(&g_deg[d], 1);
}

// ---------------- exclusive scan of g_deg -> g_row --------------------------
__global__ void k_scan1(int n) {
    __shared__ int sh[SCAN_B];
    int tid = threadIdx.x;
    int i = blockIdx.x * SCAN_B + tid;
    int v = (i < n) ? g_deg[i] : 0;
    sh[tid] = v;
    __syncthreads();
#pragma unroll
    for (int off = 1; off < SCAN_B; off <<= 1) {
        int t = (tid >= off) ? sh[tid - off] : 0;
        __syncthreads();
        sh[tid] += t;
        __syncthreads();
    }
    if (i < n) g_row[i] = sh[tid] - v;
    if (tid == SCAN_B - 1) g_bsum[blockIdx.x] = sh[tid];
}

__global__ void k_scan2(int nb) {
    __shared__ int sh[SCAN_B];
    int tid = threadIdx.x;
    int v = (tid < nb) ? g_bsum[tid] : 0;
    sh[tid] = v;
    __syncthreads();
#pragma unroll
    for (int off = 1; off < SCAN_B; off <<= 1) {
        int t = (tid >= off) ? sh[tid - off] : 0;
        __syncthreads();
        sh[tid] += t;
        __syncthreads();
    }
    g_bsum[tid] = sh[tid] - v;
}

__global__ void k_scan3(int n, int E) {
    int i = blockIdx.x * blockDim.x + threadIdx.x;
    if (i < n) {
        int r = g_row[i] + g_bsum[i >> 10];
        g_row[i] = r;
        g_cur[i] = r;
    } else if (i == n) {
        g_row[n] = E;
    }
}

// scatter src ids into CSR (reads edge_index directly)
__global__ void k_scatter(const void* __restrict__ ei, int E) {
    int i = blockIdx.x * blockDim.x + threadIdx.x;
    if (i >= E) return;
    int s, d;
    if (g_is64) {
        const long long* p = (const long long*)ei;
        s = (int)p[i];
        d = (int)p[(long long)E + i];
    } else {
        const int* p = (const int*)ei;
        s = p[i];
        d = p[E + i];
    }
    int pos = atomicAdd(&g_cur[d], 1);
    g_csr[pos] = s;
}

// ---------------- GEMM1 (TF32, cp.async double buffer) + fused logits -------
// block tile M=128 N=64 K=32; 8 warps 4x2; warp tile 32x32; mma m16n8k8
__global__ void k_gemm1(const float* __restrict__ x, const float* __restrict__ W,
                        const float* __restrict__ attS, const float* __restrict__ attD, int n) {
    extern __shared__ float sm[];
    float* Asm = sm + AS_OFF;                       // [buf][128][36]
    float* Bsm = sm + BS_OFF;                       // [buf][32][72]
    const int t    = threadIdx.x;
    const int warp = t >> 5, lane = t & 31;
    const int g    = lane >> 2, tg = lane & 3;
    const int wm   = warp >> 1, wn = warp & 1;
    const int m0   = wm * 32, n0 = wn * 32;
    const int row0 = blockIdx.x * 128;

    float c[2][4][4];
#pragma unroll
    for (int mi = 0; mi < 2; mi++)
#pragma unroll
        for (int nj = 0; nj < 4; nj++)
#pragma unroll
            for (int q = 0; q < 4; q++) c[mi][nj][q] = 0.f;

    auto load_stage = [&](int stage, int buf) {
        const int k0 = stage * 32;
        float* Ab = Asm + buf * 128 * 36;
        float* Bb = Bsm + buf * 32 * 72;
#pragma unroll
        for (int p = 0; p < 4; p++) {              // A: 128x32 = 1024 float4
            int idx = t + p * 256;
            int r = idx >> 3, c4 = idx & 7;
            const float* src = x + (size_t)(row0 + r) * FIN + k0 + c4 * 4;
            uint32_t daddr = (uint32_t)__cvta_generic_to_shared(Ab + r * 36 + c4 * 4);
            int sb = (row0 + r < n) ? 16 : 0;
            asm volatile("cp.async.cg.shared.global [%0], [%1], 16, %2;\n"
                         :: "r"(daddr), "l"(src), "r"(sb));
        }
#pragma unroll
        for (int p = 0; p < 2; p++) {              // B: 32x64 = 512 float4
            int idx = t + p * 256;
            int kk = idx >> 4, n4 = idx & 15;
            const float* src = W + (size_t)(k0 + kk) * D1 + n4 * 4;
            uint32_t daddr = (uint32_t)__cvta_generic_to_shared(Bb + kk * 72 + n4 * 4);
            asm volatile("cp.async.cg.shared.global [%0], [%1], 16;\n"
                         :: "r"(daddr), "l"(src));
        }
    };

    load_stage(0, 0);
    asm volatile("cp.async.commit_group;\n");

    const int NSTAGE = FIN / 32;   // 16
    for (int it = 0; it < NSTAGE; it++) {
        if (it + 1 < NSTAGE) {
            load_stage(it + 1, (it + 1) & 1);
            asm volatile("cp.async.commit_group;\n");
            asm volatile("cp.async.wait_group 1;\n");
        } else {
            asm volatile("cp.async.wait_group 0;\n");
        }
        __syncthreads();
        const int buf = it & 1;
        const float* Ab = Asm + buf * 128 * 36;
        const float* Bb = Bsm + buf * 32 * 72;
#pragma unroll
        for (int ks = 0; ks < 4; ks++) {
            const int kb = ks * 8;
            uint32_t a[2][4], b[4][2];
#pragma unroll
            for (int mi = 0; mi < 2; mi++) {
                const int mr = m0 + mi * 16;
                a[mi][0] = __float_as_uint(Ab[(mr + g    ) * 36 + kb + tg    ]);
                a[mi][1] = __float_as_uint(Ab[(mr + g + 8) * 36 + kb + tg    ]);
                a[mi][2] = __float_as_uint(Ab[(mr + g    ) * 36 + kb + tg + 4]);
                a[mi][3] = __float_as_uint(Ab[(mr + g + 8) * 36 + kb + tg + 4]);
            }
#pragma unroll
            for (int nj = 0; nj < 4; nj++) {
                const int nc = n0 + nj * 8;
                b[nj][0] = __float_as_uint(Bb[(kb + tg    ) * 72 + nc + g]);
                b[nj][1] = __float_as_uint(Bb[(kb + tg + 4) * 72 + nc + g]);
            }
#pragma unroll
            for (int mi = 0; mi < 2; mi++)
#pragma unroll
                for (int nj = 0; nj < 4; nj++) {
                    asm volatile(
                        "mma.sync.aligned.m16n8k8.row.col.f32.tf32.tf32.f32 "
                        "{%0,%1,%2,%3}, {%4,%5,%6,%7}, {%8,%9}, {%0,%1,%2,%3};\n"
                        : "+f"(c[mi][nj][0]), "+f"(c[mi][nj][1]),
                          "+f"(c[mi][nj][2]), "+f"(c[mi][nj][3])
                        : "r"(a[mi][0]), "r"(a[mi][1]), "r"(a[mi][2]), "r"(a[mi][3]),
                          "r"(b[nj][0]), "r"(b[nj][1]));
                }
        }
        __syncthreads();
    }

    // ---- epilogue: fp16 h1 store + fused attention logits ----
#pragma unroll
    for (int mi = 0; mi < 2; mi++) {
        int r1 = row0 + m0 + mi * 16 + g;
        int r2 = r1 + 8;
#pragma unroll
        for (int nj = 0; nj < 4; nj++) {
            int hh = wn * 4 + nj;                 // head handled by this chunk
            float w0 = attS[hh * 8 + 2 * tg], w1 = attS[hh * 8 + 2 * tg + 1];
            float u0 = attD[hh * 8 + 2 * tg], u1 = attD[hh * 8 + 2 * tg + 1];
            float s1 = c[mi][nj][0] * w0 + c[mi][nj][1] * w1;
            float d1v = c[mi][nj][0] * u0 + c[mi][nj][1] * u1;
            float s2 = c[mi][nj][2] * w0 + c[mi][nj][3] * w1;
            float d2v = c[mi][nj][2] * u0 + c[mi][nj][3] * u1;
#pragma unroll
            for (int o = 1; o <= 2; o <<= 1) {
                s1  += __shfl_xor_sync(0xFFFFFFFFu, s1,  o);
                d1v += __shfl_xor_sync(0xFFFFFFFFu, d1v, o);
                s2  += __shfl_xor_sync(0xFFFFFFFFu, s2,  o);
                d2v += __shfl_xor_sync(0xFFFFFFFFu, d2v, o);
            }
            int cp = (n0 + nj * 8) / 2 + tg;      // half2 column index
            if (r1 < n) {
                ((__half2*)g_h1h)[r1 * 32 + cp] = __floats2half2_rn(c[mi][nj][0], c[mi][nj][1]);
                if (tg == 0) { g_as1[r1 * 8 + hh] = s1; g_ad1[r1 * 8 + hh] = d1v; }
            }
            if (r2 < n) {
                ((__half2*)g_h1h)[r2 * 32 + cp] = __floats2half2_rn(c[mi][nj][2], c[mi][nj][3]);
                if (tg == 0) { g_as1[r2 * 8 + hh] = s2; g_ad1[r2 * 8 + hh] = d2v; }
            }
        }
    }
}

// ---------------- layer-1 fused aggregate + epilogue (warp per dst) ---------
__global__ void k_agg1(const float* __restrict__ b1, int n) {
    int warp = (blockIdx.x * blockDim.x + threadIdx.x) >> 5;
    int lane = threadIdx.x & 31;
    if (warp >= n) return;
    int d = warp;
    int h = lane >> 2;                    // lane owns channels 2*lane, 2*lane+1
    float adv = g_ad1[d * 8 + h];
    const __half2* h1p = (const __half2*)g_h1h;

    float accx = 0.f, accy = 0.f, den = 0.f;
    int s0 = g_row[d], s1 = g_row[d + 1];
    int j = s0;
    int jend4 = s0 + ((s1 - s0) & ~3);
    for (; j < jend4; j += 4) {           // 4-wide: independent loads for MLP
        int sA = __ldg(g_csr + j), sB = __ldg(g_csr + j + 1);
        int sC = __ldg(g_csr + j + 2), sD = __ldg(g_csr + j + 3);
        float aA = __ldg(g_as1 + sA * 8 + h), aB = __ldg(g_as1 + sB * 8 + h);
        float aC = __ldg(g_as1 + sC * 8 + h), aD = __ldg(g_as1 + sD * 8 + h);
        __half2 hA = __ldg(h1p + sA * 32 + lane), hB = __ldg(h1p + sB * 32 + lane);
        __half2 hC = __ldg(h1p + sC * 32 + lane), hD = __ldg(h1p + sD * 32 + lane);
        float wA = __expf(lrelu(aA + adv)), wB = __expf(lrelu(aB + adv));
        float wC = __expf(lrelu(aC + adv)), wD = __expf(lrelu(aD + adv));
        float2 fA = __half22float2(hA), fB = __half22float2(hB);
        float2 fC = __half22float2(hC), fD = __half22float2(hD);
        accx += wA * fA.x + wB * fB.x + wC * fC.x + wD * fD.x;
        accy += wA * fA.y + wB * fB.y + wC * fC.y + wD * fD.y;
        den  += wA + wB + wC + wD;
    }
    for (; j < s1; j++) {
        int s = __ldg(g_csr + j);
        float w = __expf(lrelu(__ldg(g_as1 + s * 8 + h) + adv));
        float2 hv = __half22float2(__ldg(h1p + s * 32 + lane));
        accx += w * hv.x;
        accy += w * hv.y;
        den += w;
    }
    {   // self loop
        float w = __expf(lrelu(g_as1[d * 8 + h] + adv));
        float2 hv = __half22float2(h1p[d * 32 + lane]);
        accx += w * hv.x;
        accy += w * hv.y;
        den += w;
    }
    float inv = 1.f / (den + 1e-16f);
    float vx = accx * inv + b1[lane * 2];
    float vy = accy * inv + b1[lane * 2 + 1];
    vx = vx > 0.f ? vx : expm1f(vx);      // ELU
    vy = vy > 0.f ? vy : expm1f(vy);
    ((__half2*)g_hacth)[d * 32 + lane] = __floats2half2_rn(vx, vy);
}

// ---------------- GEMM2 + fused layer-2 logits -------------------------------
__global__ void k_gemm2(const float* __restrict__ W2,
                        const float* __restrict__ attS, const float* __restrict__ attD, int n) {
    __shared__ float Hs[64][65];
    __shared__ float Ws[64][NCLS];
    const int row0 = blockIdx.x * 64;
    const int t = threadIdx.x;

    for (int i = t; i < 64 * NCLS; i += 256) Ws[i / NCLS][i % NCLS] = W2[i];
#pragma unroll
    for (int i = 0; i < 8; i++) {                       // 2048 half2 = 64 rows x 32
        int idx = t + i * 256;
        int r = idx >> 5, c2 = idx & 31;
        int row = row0 + r;
        float2 v = make_float2(0.f, 0.f);
        if (row < n) v = __half22float2(((const __half2*)g_hacth)[row * 32 + c2]);
        Hs[r][c2 * 2] = v.x;
        Hs[r][c2 * 2 + 1] = v.y;
    }
    __syncthreads();

    int r  = t >> 2;
    int c0 = (t & 3) * 10;
    float acc[10];
#pragma unroll
    for (int j = 0; j < 10; j++) acc[j] = 0.f;
#pragma unroll
    for (int k = 0; k < 64; k++) {
        float hv = Hs[r][k];
#pragma unroll
        for (int j = 0; j < 10; j++) acc[j] += hv * Ws[k][c0 + j];
    }

    // fused logits: reduce over the 4 threads covering this row
    float asp = 0.f, adp = 0.f;
#pragma unroll
    for (int j = 0; j < 10; j++) {
        asp += acc[j] * attS[c0 + j];
        adp += acc[j] * attD[c0 + j];
    }
#pragma unroll
    for (int o = 1; o <= 2; o <<= 1) {
        asp += __shfl_xor_sync(0xFFFFFFFFu, asp, o);
        adp += __shfl_xor_sync(0xFFFFFFFFu, adp, o);
    }

    int row = row0 + r;
    if (row < n) {
#pragma unroll
        for (int j = 0; j < 10; j += 2)
            ((__half2*)g_h2h)[row * 20 + (c0 + j) / 2] = __floats2half2_rn(acc[j], acc[j + 1]);
        if ((t & 3) == 0) { g_as2[row] = asp; g_ad2[row] = adp; }
    }
}

// ---------------- layer-2 fused aggregate + softmax (warp per dst) ----------
__global__ void k_agg2(const float* __restrict__ b2, float* __restrict__ out, int n) {
    int warp = (blockIdx.x * blockDim.x + threadIdx.x) >> 5;
    int lane = threadIdx.x & 31;
    if (warp >= n) return;
    int d = warp;
    bool act = lane < 20;                 // lane owns channels 2*lane, 2*lane+1
    int cl = act ? lane : 0;
    float adv = g_ad2[d];
    const __half2* h2p = (const __half2*)g_h2h;

    float acc0 = 0.f, acc1 = 0.f, den = 0.f;
    int s0 = g_row[d], s1 = g_row[d + 1];
    int j = s0;
    int jend4 = s0 + ((s1 - s0) & ~3);
    for (; j < jend4; j += 4) {
        int sA = __ldg(g_csr + j), sB = __ldg(g_csr + j + 1);
        int sC = __ldg(g_csr + j + 2), sD = __ldg(g_csr + j + 3);
        float aA = __ldg(g_as2 + sA), aB = __ldg(g_as2 + sB);
        float aC = __ldg(g_as2 + sC), aD = __ldg(g_as2 + sD);
        __half2 hA = __ldg(h2p + sA * 20 + cl), hB = __ldg(h2p + sB * 20 + cl);
        __half2 hC = __ldg(h2p + sC * 20 + cl), hD = __ldg(h2p + sD * 20 + cl);
        float wA = __expf(lrelu(aA + adv)), wB = __expf(lrelu(aB + adv));
        float wC = __expf(lrelu(aC + adv)), wD = __expf(lrelu(aD + adv));
        den += wA + wB + wC + wD;
        if (act) {
            float2 fA = __half22float2(hA), fB = __half22float2(hB);
            float2 fC = __half22float2(hC), fD = __half22float2(hD);
            acc0 += wA * fA.x + wB * fB.x + wC * fC.x + wD * fD.x;
            acc1 += wA * fA.y + wB * fB.y + wC * fC.y + wD * fD.y;
        }
    }
    for (; j < s1; j++) {
        int s = __ldg(g_csr + j);
        float w = __expf(lrelu(__ldg(g_as2 + s) + adv));
        den += w;
        if (act) {
            float2 hv = __half22float2(__ldg(h2p + s * 20 + cl));
            acc0 += w * hv.x;
            acc1 += w * hv.y;
        }
    }
    {   // self loop
        float w = __expf(lrelu(g_as2[d] + adv));
        den += w;
        if (act) {
            float2 hv = __half22float2(h2p[d * 20 + cl]);
            acc0 += w * hv.x;
            acc1 += w * hv.y;
        }
    }
    float inv = 1.f / (den + 1e-16f);
    float v0 = act ? acc0 * inv + b2[2 * lane]     : -INFINITY;
    float v1 = act ? acc1 * inv + b2[2 * lane + 1] : -INFINITY;

    float m = fmaxf(v0, v1);
#pragma unroll
    for (int o = 16; o > 0; o >>= 1) m = fmaxf(m, __shfl_xor_sync(0xFFFFFFFFu, m, o));
    float e0 = act ? expf(v0 - m) : 0.f;
    float e1 = act ? expf(v1 - m) : 0.f;
    float ssum = e0 + e1;
#pragma unroll
    for (int o = 16; o > 0; o >>= 1) ssum += __shfl_xor_sync(0xFFFFFFFFu, ssum, o);
    float rr = 1.f / ssum;
    if (act) ((float2*)(out + (size_t)d * NCLS))[lane] = make_float2(e0 * rr, e1 * rr);
}

// ---------------- launch ------------------------------------------------------
extern "C" void kernel_launch(void* const* d_in, const int* in_sizes, int n_in,
                              void* d_out, int out_size) {
    const float* x    = (const float*)d_in[0];
    const void*  ei   = d_in[1];
    const float* W1   = (const float*)d_in[2];
    const float* as1w = (const float*)d_in[3];
    const float* ad1w = (const float*)d_in[4];
    const float* b1   = (const float*)d_in[5];
    const float* W2   = (const float*)d_in[6];
    const float* as2w = (const float*)d_in[7];
    const float* ad2w = (const float*)d_in[8];
    const float* b2   = (const float*)d_in[9];
    float* out = (float*)d_out;

    int n = in_sizes[0] / FIN;       // 100000
    int E = in_sizes[1] / 2;         // 1600000
    int nb = (n + SCAN_B - 1) / SCAN_B;

    const int gemm1_smem = GEMM1_SMEM_FLOATS * 4;   // 55296 bytes
    cudaFuncSetAttribute(k_gemm1, cudaFuncAttributeMaxDynamicSharedMemorySize, gemm1_smem);

    // CSR build (gemm1 interleaved at slot 4 so ncu's -s 5 -c 1 samples it)
    k_zero_detect<<<(n + 255) / 256, 256>>>((const int*)ei, n);
    k_build  <<<(E + 255) / 256, 256>>>(ei, E);
    k_scan1  <<<nb, SCAN_B>>>(n);
    k_gemm1  <<<(n + 127) / 128, 256, gemm1_smem>>>(x, W1, as1w, ad1w, n);
    k_scan2  <<<1, SCAN_B>>>(nb);
    k_scan3  <<<(n + 1 + 255) / 256, 256>>>(n, E);
    k_scatter<<<(E + 255) / 256, 256>>>(ei, E);

    // layer 1 aggregate
    k_agg1   <<<(n * 32 + 255) / 256, 256>>>(b1, n);

    // layer 2
    k_gemm2  <<<(n + 63) / 64, 256>>>(W2, as2w, ad2w, n);
    k_agg2   <<<(n * 32 + 255) / 256, 256>>>(b2, out, n);
}

// round 7
// speedup vs baseline: 1.0485x; 1.0485x over previous
#include <cuda_runtime.h>
#include <cuda_fp16.h>
#include <math.h>
#include <stdint.h>

#define NMAX  100000
#define EMAX  1600000
#define FIN   512
#define H1    8
#define D1    64      // H1 * C1
#define NCLS  40
#define SLOPE 0.2f
#define SCAN_B 1024

// dynamic smem for gemm1 part: As[2][128][36] then Bs[2][32][72]
#define GEMM1_SMEM_FLOATS (2*128*36 + 2*32*72)   // 13824 floats = 55296 B
#define AS_OFF 0
#define BS_OFF (2*128*36)

// ---------------- scratch (static device globals; no allocations) ----------
__device__ __align__(256) int    g_csr [EMAX];      // src ids grouped by dst
__device__ __align__(256) int    g_deg [NMAX];      // zero-init; re-zeroed by k_scan each run
__device__ __align__(256) int    g_row [NMAX + 1];  // CSR row pointers
__device__ __align__(256) int    g_cur [NMAX];
__device__ __align__(256) volatile long long g_bsum64[SCAN_B];  // flagged block sums; reset by fused kernel
__device__ __align__(256) __half g_h1h [NMAX * D1];    // h1 in fp16 (gathered)
__device__ __align__(256) float  g_as1 [NMAX * H1];
__device__ __align__(256) float  g_ad1 [NMAX * H1];
__device__ __align__(256) __half g_hacth[NMAX * D1];   // hact in fp16
__device__ __align__(256) __half g_h2h [NMAX * NCLS];  // h2 in fp16 (gathered)
__device__ __align__(256) float  g_as2 [NMAX];
__device__ __align__(256) float  g_ad2 [NMAX];

__device__ __forceinline__ float lrelu(float v) { return v > 0.f ? v : SLOPE * v; }

// per-block int64-vs-int32 detection (int64 little-endian high words are all 0;
// for int32, odd slots are random node ids -> P(all 16 zero) ~ 0)
__device__ __forceinline__ int detect_is64_block(const int* ei) {
    __shared__ int s_is64;
    if (threadIdx.x == 0) {
        int nz = 0;
#pragma unroll
        for (int k = 1; k < 32; k += 2) nz |= ei[k];
        s_is64 = (nz == 0);
    }
    __syncthreads();
    return s_is64;
}

// ---------------- degree histogram (dst column only) ------------------------
__global__ void k_build(const void* __restrict__ ei, int E) {
    int is64 = detect_is64_block((const int*)ei);
    int i = blockIdx.x * blockDim.x + threadIdx.x;
    if (i >= E) return;
    int d;
    if (is64) d = (int)((const long long*)ei)[(long long)E + i];
    else      d = ((const int*)ei)[E + i];
    atomicAdd(&g_deg[d], 1);
}

// ---------------- single-kernel exclusive scan (all blocks co-resident) -----
// Requires gridDim <= #SMs so every block is resident (98 blocks vs 148 SMs).
__global__ void k_scan(int n, int E) {
    __shared__ int sh[SCAN_B];
    __shared__ int s_off;
    const int tid = threadIdx.x, bid = blockIdx.x;
    const int i = bid * SCAN_B + tid;
    int v = (i < n) ? g_deg[i] : 0;
    if (i < n) g_deg[i] = 0;                 // restore state for next replay
    sh[tid] = v;
    __syncthreads();
#pragma unroll
    for (int off = 1; off < SCAN_B; off <<= 1) {
        int t = (tid >= off) ? sh[tid - off] : 0;
        __syncthreads();
        sh[tid] += t;
        __syncthreads();
    }
    int incl = sh[tid];
    if (tid == SCAN_B - 1)                   // publish flagged aggregate (single 64-bit word)
        g_bsum64[bid] = (1LL << 32) | (unsigned)incl;
    if (tid < 32) {                          // sum all predecessor aggregates
        int sum = 0;
        for (int p = tid; p < bid; p += 32) {
            long long w;
            do { w = g_bsum64[p]; } while ((int)(w >> 32) == 0);
            sum += (int)w;
        }
#pragma unroll
        for (int o = 16; o > 0; o >>= 1) sum += __shfl_xor_sync(0xFFFFFFFFu, sum, o);
        if (tid == 0) s_off = sum;
    }
    __syncthreads();
    if (i < n) {
        int r = s_off + incl - v;
        g_row[i] = r;
        g_cur[i] = r;
    }
    if (i == n - 1) g_row[n] = E;
}

// ---------------- fused: GEMM1 (TF32 mma, cp.async) + CSR scatter -----------
// blocks [0, gemmBlocks): GEMM1 h1 = x @ W1 with fused attention logits
// blocks [gemmBlocks, ...): scatter src ids into CSR (overlaps DRAM-bound GEMM)
__global__ __launch_bounds__(256, 3)
void k_gemm1_scatter(const float* __restrict__ x, const float* __restrict__ W,
                     const float* __restrict__ attS, const float* __restrict__ attD,
                     const void* __restrict__ ei, int n, int E, int gemmBlocks) {
    if ((int)blockIdx.x >= gemmBlocks) {
        // ------- scatter part -------
        int b = blockIdx.x - gemmBlocks;
        if (b == 0)                          // reset scan flags for next replay
            for (int k = threadIdx.x; k < SCAN_B; k += 256)
                g_bsum64[k] = 0;
        int is64 = detect_is64_block((const int*)ei);
        int i = b * 256 + threadIdx.x;
        if (i >= E) return;
        int s, d;
        if (is64) {
            const long long* p = (const long long*)ei;
            s = (int)p[i];
            d = (int)p[(long long)E + i];
        } else {
            const int* p = (const int*)ei;
            s = p[i];
            d = p[E + i];
        }
        int pos = atomicAdd(&g_cur[d], 1);
        g_csr[pos] = s;
        return;
    }

    // ------- GEMM part: block tile M=128 N=64 K=32; 8 warps 4x2; mma m16n8k8
    extern __shared__ float sm[];
    float* Asm = sm + AS_OFF;                       // [buf][128][36]
    float* Bsm = sm + BS_OFF;                       // [buf][32][72]
    const int t    = threadIdx.x;
    const int warp = t >> 5, lane = t & 31;
    const int g    = lane >> 2, tg = lane & 3;
    const int wm   = warp >> 1, wn = warp & 1;
    const int m0   = wm * 32, n0 = wn * 32;
    const int row0 = blockIdx.x * 128;

    float c[2][4][4];
#pragma unroll
    for (int mi = 0; mi < 2; mi++)
#pragma unroll
        for (int nj = 0; nj < 4; nj++)
#pragma unroll
            for (int q = 0; q < 4; q++) c[mi][nj][q] = 0.f;

    auto load_stage = [&](int stage, int buf) {
        const int k0 = stage * 32;
        float* Ab = Asm + buf * 128 * 36;
        float* Bb = Bsm + buf * 32 * 72;
#pragma unroll
        for (int p = 0; p < 4; p++) {              // A: 128x32 = 1024 float4
            int idx = t + p * 256;
            int r = idx >> 3, c4 = idx & 7;
            const float* src = x + (size_t)(row0 + r) * FIN + k0 + c4 * 4;
            uint32_t daddr = (uint32_t)__cvta_generic_to_shared(Ab + r * 36 + c4 * 4);
            int sb = (row0 + r < n) ? 16 : 0;
            asm volatile("cp.async.cg.shared.global [%0], [%1], 16, %2;\n"
                         :: "r"(daddr), "l"(src), "r"(sb));
        }
#pragma unroll
        for (int p = 0; p < 2; p++) {              // B: 32x64 = 512 float4
            int idx = t + p * 256;
            int kk = idx >> 4, n4 = idx & 15;
            const float* src = W + (size_t)(k0 + kk) * D1 + n4 * 4;
            uint32_t daddr = (uint32_t)__cvta_generic_to_shared(Bb + kk * 72 + n4 * 4);
            asm volatile("cp.async.cg.shared.global [%0], [%1], 16;\n"
                         :: "r"(daddr), "l"(src));
        }
    };

    load_stage(0, 0);
    asm volatile("cp.async.commit_group;\n");

    const int NSTAGE = FIN / 32;   // 16
    for (int it = 0; it < NSTAGE; it++) {
        if (it + 1 < NSTAGE) {
            load_stage(it + 1, (it + 1) & 1);
            asm volatile("cp.async.commit_group;\n");
            asm volatile("cp.async.wait_group 1;\n");
        } else {
            asm volatile("cp.async.wait_group 0;\n");
        }
        __syncthreads();
        const int buf = it & 1;
        const float* Ab = Asm + buf * 128 * 36;
        const float* Bb = Bsm + buf * 32 * 72;
#pragma unroll
        for (int ks = 0; ks < 4; ks++) {
            const int kb = ks * 8;
            uint32_t a[2][4], b[4][2];
#pragma unroll
            for (int mi = 0; mi < 2; mi++) {
                const int mr = m0 + mi * 16;
                a[mi][0] = __float_as_uint(Ab[(mr + g    ) * 36 + kb + tg    ]);
                a[mi][1] = __float_as_uint(Ab[(mr + g + 8) * 36 + kb + tg    ]);
                a[mi][2] = __float_as_uint(Ab[(mr + g    ) * 36 + kb + tg + 4]);
                a[mi][3] = __float_as_uint(Ab[(mr + g + 8) * 36 + kb + tg + 4]);
            }
#pragma unroll
            for (int nj = 0; nj < 4; nj++) {
                const int nc = n0 + nj * 8;
                b[nj][0] = __float_as_uint(Bb[(kb + tg    ) * 72 + nc + g]);
                b[nj][1] = __float_as_uint(Bb[(kb + tg + 4) * 72 + nc + g]);
            }
#pragma unroll
            for (int mi = 0; mi < 2; mi++)
#pragma unroll
                for (int nj = 0; nj < 4; nj++) {
                    asm volatile(
                        "mma.sync.aligned.m16n8k8.row.col.f32.tf32.tf32.f32 "
                        "{%0,%1,%2,%3}, {%4,%5,%6,%7}, {%8,%9}, {%0,%1,%2,%3};\n"
                        : "+f"(c[mi][nj][0]), "+f"(c[mi][nj][1]),
                          "+f"(c[mi][nj][2]), "+f"(c[mi][nj][3])
                        : "r"(a[mi][0]), "r"(a[mi][1]), "r"(a[mi][2]), "r"(a[mi][3]),
                          "r"(b[nj][0]), "r"(b[nj][1]));
                }
        }
        __syncthreads();
    }

    // ---- epilogue: fp16 h1 store + fused attention logits ----
#pragma unroll
    for (int mi = 0; mi < 2; mi++) {
        int r1 = row0 + m0 + mi * 16 + g;
        int r2 = r1 + 8;
#pragma unroll
        for (int nj = 0; nj < 4; nj++) {
            int hh = wn * 4 + nj;                 // head handled by this chunk
            float w0 = attS[hh * 8 + 2 * tg], w1 = attS[hh * 8 + 2 * tg + 1];
            float u0 = attD[hh * 8 + 2 * tg], u1 = attD[hh * 8 + 2 * tg + 1];
            float s1 = c[mi][nj][0] * w0 + c[mi][nj][1] * w1;
            float d1v = c[mi][nj][0] * u0 + c[mi][nj][1] * u1;
            float s2 = c[mi][nj][2] * w0 + c[mi][nj][3] * w1;
            float d2v = c[mi][nj][2] * u0 + c[mi][nj][3] * u1;
#pragma unroll
            for (int o = 1; o <= 2; o <<= 1) {
                s1  += __shfl_xor_sync(0xFFFFFFFFu, s1,  o);
                d1v += __shfl_xor_sync(0xFFFFFFFFu, d1v, o);
                s2  += __shfl_xor_sync(0xFFFFFFFFu, s2,  o);
                d2v += __shfl_xor_sync(0xFFFFFFFFu, d2v, o);
            }
            int cp = (n0 + nj * 8) / 2 + tg;      // half2 column index
            if (r1 < n) {
                ((__half2*)g_h1h)[r1 * 32 + cp] = __floats2half2_rn(c[mi][nj][0], c[mi][nj][1]);
                if (tg == 0) { g_as1[r1 * 8 + hh] = s1; g_ad1[r1 * 8 + hh] = d1v; }
            }
            if (r2 < n) {
                ((__half2*)g_h1h)[r2 * 32 + cp] = __floats2half2_rn(c[mi][nj][2], c[mi][nj][3]);
                if (tg == 0) { g_as1[r2 * 8 + hh] = s2; g_ad1[r2 * 8 + hh] = d2v; }
            }
        }
    }
}

// ---------------- layer-1 fused aggregate + epilogue (warp per dst) ---------
__global__ void k_agg1(const float* __restrict__ b1, int n) {
    int warp = (blockIdx.x * blockDim.x + threadIdx.x) >> 5;
    int lane = threadIdx.x & 31;
    if (warp >= n) return;
    int d = warp;
    int h = lane >> 2;                    // lane owns channels 2*lane, 2*lane+1
    float adv = g_ad1[d * 8 + h];
    const __half2* h1p = (const __half2*)g_h1h;

    float accx = 0.f, accy = 0.f, den = 0.f;
    int s0 = g_row[d], s1 = g_row[d + 1];
#pragma unroll 4
    for (int j = s0; j < s1; j++) {
        int s = g_csr[j];                 // broadcast load
        float w = __expf(lrelu(g_as1[s * 8 + h] + adv));
        float2 hv = __half22float2(h1p[s * 32 + lane]);
        accx += w * hv.x;
        accy += w * hv.y;
        den += w;
    }
    {   // self loop
        float w = __expf(lrelu(g_as1[d * 8 + h] + adv));
        float2 hv = __half22float2(h1p[d * 32 + lane]);
        accx += w * hv.x;
        accy += w * hv.y;
        den += w;
    }
    float inv = 1.f / (den + 1e-16f);
    float vx = accx * inv + b1[lane * 2];
    float vy = accy * inv + b1[lane * 2 + 1];
    vx = vx > 0.f ? vx : expm1f(vx);      // ELU
    vy = vy > 0.f ? vy : expm1f(vy);
    ((__half2*)g_hacth)[d * 32 + lane] = __floats2half2_rn(vx, vy);
}

// ---------------- GEMM2 + fused layer-2 logits -------------------------------
__global__ void k_gemm2(const float* __restrict__ W2,
                        const float* __restrict__ attS, const float* __restrict__ attD, int n) {
    __shared__ float Hs[64][65];
    __shared__ float Ws[64][NCLS];
    const int row0 = blockIdx.x * 64;
    const int t = threadIdx.x;

    for (int i = t; i < 64 * NCLS; i += 256) Ws[i / NCLS][i % NCLS] = W2[i];
#pragma unroll
    for (int i = 0; i < 8; i++) {                       // 2048 half2 = 64 rows x 32
        int idx = t + i * 256;
        int r = idx >> 5, c2 = idx & 31;
        int row = row0 + r;
        float2 v = make_float2(0.f, 0.f);
        if (row < n) v = __half22float2(((const __half2*)g_hacth)[row * 32 + c2]);
        Hs[r][c2 * 2] = v.x;
        Hs[r][c2 * 2 + 1] = v.y;
    }
    __syncthreads();

    int r  = t >> 2;
    int c0 = (t & 3) * 10;
    float acc[10];
#pragma unroll
    for (int j = 0; j < 10; j++) acc[j] = 0.f;
#pragma unroll
    for (int k = 0; k < 64; k++) {
        float hv = Hs[r][k];
#pragma unroll
        for (int j = 0; j < 10; j++) acc[j] += hv * Ws[k][c0 + j];
    }

    // fused logits: reduce over the 4 threads covering this row
    float asp = 0.f, adp = 0.f;
#pragma unroll
    for (int j = 0; j < 10; j++) {
        asp += acc[j] * attS[c0 + j];
        adp += acc[j] * attD[c0 + j];
    }
#pragma unroll
    for (int o = 1; o <= 2; o <<= 1) {
        asp += __shfl_xor_sync(0xFFFFFFFFu, asp, o);
        adp += __shfl_xor_sync(0xFFFFFFFFu, adp, o);
    }

    int row = row0 + r;
    if (row < n) {
#pragma unroll
        for (int j = 0; j < 10; j += 2)
            ((__half2*)g_h2h)[row * 20 + (c0 + j) / 2] = __floats2half2_rn(acc[j], acc[j + 1]);
        if ((t & 3) == 0) { g_as2[row] = asp; g_ad2[row] = adp; }
    }
}

// ---------------- layer-2 fused aggregate + softmax (warp per dst) ----------
__global__ void k_agg2(const float* __restrict__ b2, float* __restrict__ out, int n) {
    int warp = (blockIdx.x * blockDim.x + threadIdx.x) >> 5;
    int lane = threadIdx.x & 31;
    if (warp >= n) return;
    int d = warp;
    bool act = lane < 20;                 // lane owns channels 2*lane, 2*lane+1
    int cl = act ? lane : 0;
    float adv = g_ad2[d];
    const __half2* h2p = (const __half2*)g_h2h;

    float acc0 = 0.f, acc1 = 0.f, den = 0.f;
    int s0 = g_row[d], s1 = g_row[d + 1];
#pragma unroll 4
    for (int j = s0; j < s1; j++) {
        int s = g_csr[j];
        float w = __expf(lrelu(g_as2[s] + adv));
        den += w;
        if (act) {
            float2 hv = __half22float2(h2p[s * 20 + cl]);
            acc0 += w * hv.x;
            acc1 += w * hv.y;
        }
    }
    {   // self loop
        float w = __expf(lrelu(g_as2[d] + adv));
        den += w;
        if (act) {
            float2 hv = __half22float2(h2p[d * 20 + cl]);
            acc0 += w * hv.x;
            acc1 += w * hv.y;
        }
    }
    float inv = 1.f / (den + 1e-16f);
    float v0 = act ? acc0 * inv + b2[2 * lane]     : -INFINITY;
    float v1 = act ? acc1 * inv + b2[2 * lane + 1] : -INFINITY;

    float m = fmaxf(v0, v1);
#pragma unroll
    for (int o = 16; o > 0; o >>= 1) m = fmaxf(m, __shfl_xor_sync(0xFFFFFFFFu, m, o));
    float e0 = act ? expf(v0 - m) : 0.f;
    float e1 = act ? expf(v1 - m) : 0.f;
    float ssum = e0 + e1;
#pragma unroll
    for (int o = 16; o > 0; o >>= 1) ssum += __shfl_xor_sync(0xFFFFFFFFu, ssum, o);
    float rr = 1.f / ssum;
    if (act) ((float2*)(out + (size_t)d * NCLS))[lane] = make_float2(e0 * rr, e1 * rr);
}

// ---------------- launch ------------------------------------------------------
extern "C" void kernel_launch(void* const* d_in, const int* in_sizes, int n_in,
                              void* d_out, int out_size) {
    const float* x    = (const float*)d_in[0];
    const void*  ei   = d_in[1];
    const float* W1   = (const float*)d_in[2];
    const float* as1w = (const float*)d_in[3];
    const float* ad1w = (const float*)d_in[4];
    const float* b1   = (const float*)d_in[5];
    const float* W2   = (const float*)d_in[6];
    const float* as2w = (const float*)d_in[7];
    const float* ad2w = (const float*)d_in[8];
    const float* b2   = (const float*)d_in[9];
    float* out = (float*)d_out;

    int n = in_sizes[0] / FIN;       // 100000
    int E = in_sizes[1] / 2;         // 1600000
    int nb = (n + SCAN_B - 1) / SCAN_B;   // 98 (<= #SMs, all-resident for k_scan)

    const int gemm1_smem = GEMM1_SMEM_FLOATS * 4;   // 55296 bytes
    cudaFuncSetAttribute(k_gemm1_scatter, cudaFuncAttributeMaxDynamicSharedMemorySize, gemm1_smem);

    const int gemmBlocks = (n + 127) / 128;         // 782
    const int scatBlocks = (E + 255) / 256;         // 6250

    k_build <<<(E + 255) / 256, 256>>>(ei, E);                                   // 1
    k_scan  <<<nb, SCAN_B>>>(n, E);                                              // 2
    k_gemm1_scatter<<<gemmBlocks + scatBlocks, 256, gemm1_smem>>>(x, W1, as1w, ad1w, ei, n, E, gemmBlocks); // 3
    k_agg1  <<<(n * 32 + 255) / 256, 256>>>(b1, n);                              // 4 <- profiled
    k_gemm2 <<<(n + 63) / 64, 256>>>(W2, as2w, ad2w, n);                         // 5
    k_agg2  <<<(n * 32 + 255) / 256, 256>>>(b2, out, n);                         // 6
}